// round 1
// baseline (speedup 1.0000x reference)
#include <cuda_runtime.h>

#define IMG_H 256
#define IMG_W 256
#define NPIX (8 * IMG_H * IMG_W)
#define NVOX 1000000

// Scratch: fused (mask, depth) per pixel so each vertex gather is a single LDG.64.
__device__ float2 g_md[NPIX];

__global__ void pack_md_kernel(const float* __restrict__ mask,
                               const float* __restrict__ depth) {
    int i = blockIdx.x * blockDim.x + threadIdx.x;
    if (i < NPIX) g_md[i] = make_float2(mask[i], depth[i]);
}

__global__ __launch_bounds__(256) void octree_kernel(
    const float* __restrict__ pts,
    const float* __restrict__ Km,
    const int*   __restrict__ bids,
    const float* __restrict__ gsz,
    float2*      __restrict__ out)
{
    int n = blockIdx.x * blockDim.x + threadIdx.x;
    if (n >= NVOX) return;

    float px = pts[3 * n + 0];
    float py = pts[3 * n + 1];
    float pz = pts[3 * n + 2];
    int   bid = bids[n];

    float gs = gsz[0];
    float fx = Km[0], cx = Km[2];
    float fy = Km[4], cy = Km[5];

    float h  = 0.5f * gs;                 // gs * 0.5 is exact
    float xm = px - h, xp = px + h;
    float ym = py - h, yp = py + h;
    float zm = fmaxf(pz - h, 1e-6f);
    float zp = fmaxf(pz + h, 1e-6f);

    // 4 distinct u values: (x in {m,p}) x (z in {m,p})
    float u_mm = __fdiv_rn(fx * xm, zm) + cx;   // z=m, x=m
    float u_mp = __fdiv_rn(fx * xp, zm) + cx;   // z=m, x=p
    float u_pm = __fdiv_rn(fx * xm, zp) + cx;   // z=p, x=m
    float u_pp = __fdiv_rn(fx * xp, zp) + cx;   // z=p, x=p
    // 4 distinct v values: (y in {m,p}) x (z in {m,p})
    float v_mm = __fdiv_rn(fy * ym, zm) + cy;
    float v_mp = __fdiv_rn(fy * yp, zm) + cy;
    float v_pm = __fdiv_rn(fy * ym, zp) + cy;
    float v_pp = __fdiv_rn(fy * yp, zp) + cy;

    // round-half-even (matches jnp.round) + clip
    int pu_mm = min(max(__float2int_rn(u_mm), 0), IMG_W - 1);
    int pu_mp = min(max(__float2int_rn(u_mp), 0), IMG_W - 1);
    int pu_pm = min(max(__float2int_rn(u_pm), 0), IMG_W - 1);
    int pu_pp = min(max(__float2int_rn(u_pp), 0), IMG_W - 1);
    int pv_mm = min(max(__float2int_rn(v_mm), 0), IMG_H - 1);
    int pv_mp = min(max(__float2int_rn(v_mp), 0), IMG_H - 1);
    int pv_pm = min(max(__float2int_rn(v_pm), 0), IMG_H - 1);
    int pv_pp = min(max(__float2int_rn(v_pp), 0), IMG_H - 1);

    int base = bid << 16;   // bid * 256 * 256

    // Vertex order matches GRID_OFFSET; weight = occurrence count in FACE_OFFSET.
    // v0:(m,m,zm) v1:(p,m,zm) v2:(p,p,zm) v3:(m,p,zm)
    // v4:(m,m,zp) v5:(p,m,zp) v6:(p,p,zp) v7:(m,p,zp)
    int idx[8];
    idx[0] = base + pv_mm * IMG_W + pu_mm;
    idx[1] = base + pv_mm * IMG_W + pu_mp;
    idx[2] = base + pv_mp * IMG_W + pu_mp;
    idx[3] = base + pv_mp * IMG_W + pu_mm;
    idx[4] = base + pv_pm * IMG_W + pu_pm;
    idx[5] = base + pv_pm * IMG_W + pu_pp;
    idx[6] = base + pv_pp * IMG_W + pu_pp;
    idx[7] = base + pv_pp * IMG_W + pu_pm;

    // Issue all 8 gathers first for MLP
    float2 md[8];
#pragma unroll
    for (int i = 0; i < 8; i++) md[i] = __ldg(&g_md[idx[i]]);

    const float w[8] = {5.f, 4.f, 5.f, 4.f, 5.f, 4.f, 5.f, 4.f};
    float cover = 0.f, free_acc = 0.f;
#pragma unroll
    for (int i = 0; i < 8; i++) {
        float z = (i < 4) ? zm : zp;
        // sigmoid((d - z)/tau) = 1 / (1 + exp((z - d) * 20))
        float e = __expf((z - md[i].y) * 20.0f);
        float s = 1.0f / (1.0f + e);
        cover    += w[i] * md[i].x;
        free_acc += w[i] * s;
    }
    const float inv36 = 1.0f / 36.0f;
    out[n] = make_float2(cover * inv36, free_acc * inv36);
}

extern "C" void kernel_launch(void* const* d_in, const int* in_sizes, int n_in,
                              void* d_out, int out_size) {
    const float* pts   = (const float*)d_in[0];
    const float* mask  = (const float*)d_in[1];
    const float* depth = (const float*)d_in[2];
    const float* Km    = (const float*)d_in[3];
    const int*   bids  = (const int*)  d_in[4];
    const float* gsz   = (const float*)d_in[5];
    float2*      out   = (float2*)d_out;

    pack_md_kernel<<<(NPIX + 255) / 256, 256>>>(mask, depth);
    octree_kernel<<<(NVOX + 255) / 256, 256>>>(pts, Km, bids, gsz, out);
}

// round 3
// speedup vs baseline: 1.0746x; 1.0746x over previous
#include <cuda_runtime.h>

#define IMG_H 256
#define IMG_W 256
#define NPIX (8 * IMG_H * IMG_W)
#define NVOX 1000000

// Scratch: packed (depth with mask in mantissa LSB), tiled 8x8 for 2D locality.
// Texel layout: idx = (b<<16) | ((v>>3)<<11) | ((u>>3)<<6) | ((v&7)<<3) | (u&7)
// -> one 8x8 pixel tile = 64 texels * 4B = 256B = 2 cache lines.
__device__ unsigned g_md[NPIX];

__global__ void pack_md_kernel(const float* __restrict__ mask,
                               const float* __restrict__ depth) {
    int i = blockIdx.x * blockDim.x + threadIdx.x;
    if (i >= NPIX) return;
    int b   = i >> 16;
    int rem = i & 0xFFFF;
    int v   = rem >> 8;
    int u   = rem & 0xFF;
    unsigned mbit = (mask[i] != 0.0f) ? 1u : 0u;
    unsigned bits = (__float_as_uint(depth[i]) & ~1u) | mbit;
    int dst = (b << 16) | ((v >> 3) << 11) | ((u >> 3) << 6) | ((v & 7) << 3) | (u & 7);
    g_md[dst] = bits;
}

__device__ __forceinline__ int upart(int pu) {
    return ((pu >> 3) << 6) | (pu & 7);
}
__device__ __forceinline__ int vpart(int pv) {
    return ((pv >> 3) << 11) | ((pv & 7) << 3);
}

__global__ __launch_bounds__(256) void octree_kernel(
    const float* __restrict__ pts,
    const float* __restrict__ Km,
    const int*   __restrict__ bids,
    const float* __restrict__ gsz,
    float2*      __restrict__ out)
{
    int n = blockIdx.x * blockDim.x + threadIdx.x;
    if (n >= NVOX) return;

    float px = pts[3 * n + 0];
    float py = pts[3 * n + 1];
    float pz = pts[3 * n + 2];
    int   bid = bids[n];

    float gs = gsz[0];
    float fx = Km[0], cx = Km[2];
    float fy = Km[4], cy = Km[5];

    float h  = 0.5f * gs;
    float xm = px - h, xp = px + h;
    float ym = py - h, yp = py + h;
    float zm = fmaxf(pz - h, 1e-6f);
    float zp = fmaxf(pz + h, 1e-6f);

    // 4 distinct u and 4 distinct v values (x/y in {m,p}) x (z in {m,p})
    float u_mm = __fdiv_rn(fx * xm, zm) + cx;
    float u_mp = __fdiv_rn(fx * xp, zm) + cx;
    float u_pm = __fdiv_rn(fx * xm, zp) + cx;
    float u_pp = __fdiv_rn(fx * xp, zp) + cx;
    float v_mm = __fdiv_rn(fy * ym, zm) + cy;
    float v_mp = __fdiv_rn(fy * yp, zm) + cy;
    float v_pm = __fdiv_rn(fy * ym, zp) + cy;
    float v_pp = __fdiv_rn(fy * yp, zp) + cy;

    // round-half-even (matches jnp.round) + clip
    int pu_mm = min(max(__float2int_rn(u_mm), 0), IMG_W - 1);
    int pu_mp = min(max(__float2int_rn(u_mp), 0), IMG_W - 1);
    int pu_pm = min(max(__float2int_rn(u_pm), 0), IMG_W - 1);
    int pu_pp = min(max(__float2int_rn(u_pp), 0), IMG_W - 1);
    int pv_mm = min(max(__float2int_rn(v_mm), 0), IMG_H - 1);
    int pv_mp = min(max(__float2int_rn(v_mp), 0), IMG_H - 1);
    int pv_pm = min(max(__float2int_rn(v_pm), 0), IMG_H - 1);
    int pv_pp = min(max(__float2int_rn(v_pp), 0), IMG_H - 1);

    int base = bid << 16;

    int ua = upart(pu_mm), ub = upart(pu_mp);
    int uc = upart(pu_pm), ud = upart(pu_pp);
    int va = vpart(pv_mm), vb = vpart(pv_mp);
    int vc = vpart(pv_pm), vd = vpart(pv_pp);

    // Vertex order per GRID_OFFSET; weight = occurrence count in FACE_OFFSET.
    int idx[8];
    idx[0] = base + va + ua;   // v0: (xm, ym, zm)  w=5
    idx[1] = base + va + ub;   // v1: (xp, ym, zm)  w=4
    idx[2] = base + vb + ub;   // v2: (xp, yp, zm)  w=5
    idx[3] = base + vb + ua;   // v3: (xm, yp, zm)  w=4
    idx[4] = base + vc + uc;   // v4: (xm, ym, zp)  w=5
    idx[5] = base + vc + ud;   // v5: (xp, ym, zp)  w=4
    idx[6] = base + vd + ud;   // v6: (xp, yp, zp)  w=5
    idx[7] = base + vd + uc;   // v7: (xm, yp, zp)  w=4

    // Issue all 8 gathers up front for MLP
    unsigned md[8];
#pragma unroll
    for (int i = 0; i < 8; i++) md[i] = __ldg(&g_md[idx[i]]);

    const int wgt[8] = {5, 4, 5, 4, 5, 4, 5, 4};
    int   cover_i = 0;
    float free_acc = 0.f;
#pragma unroll
    for (int i = 0; i < 8; i++) {
        float z = (i < 4) ? zm : zp;
        float d = __uint_as_float(md[i] & ~1u);
        // sigmoid((d - z)/tau) = 1 / (1 + exp((z - d) * 20))
        float e = __expf((z - d) * 20.0f);
        float s = 1.0f / (1.0f + e);
        cover_i  += wgt[i] * (int)(md[i] & 1u);
        free_acc += (float)wgt[i] * s;
    }
    const float inv36 = 1.0f / 36.0f;
    out[n] = make_float2((float)cover_i * inv36, free_acc * inv36);
}

extern "C" void kernel_launch(void* const* d_in, const int* in_sizes, int n_in,
                              void* d_out, int out_size) {
    const float* pts   = (const float*)d_in[0];
    const float* mask  = (const float*)d_in[1];
    const float* depth = (const float*)d_in[2];
    const float* Km    = (const float*)d_in[3];
    const int*   bids  = (const int*)  d_in[4];
    const float* gsz   = (const float*)d_in[5];
    float2*      out   = (float2*)d_out;

    pack_md_kernel<<<(NPIX + 255) / 256, 256>>>(mask, depth);
    octree_kernel<<<(NVOX + 255) / 256, 256>>>(pts, Km, bids, gsz, out);
}